// round 9
// baseline (speedup 1.0000x reference)
#include <cuda_runtime.h>
#include <cstdint>

#define STRIDE   10
#define NF       128
#define PAIRS    8128      // 128*127/2
#define NTASKS   12        // 16-row blocks x 64-col chunks covering lower triangle
#define THREADS  384       // 12 warps, exactly 1 task each
#define WPC      4         // windows per CTA (pipelined)
#define SLAB     (STRIDE * NF)   // 1280 floats = 5120 B
#define NBUF     3         // smem ring depth

// task -> (16-row block index, 64-col chunk index)
__constant__ unsigned char c_bi[NTASKS] = {0,1,2,3,4,4,5,5,6,6,7,7};
__constant__ unsigned char c_jc[NTASKS] = {0,0,0,0,0,1,0,1,0,1,0,1};

__device__ __forceinline__ void cp_async16(uint32_t saddr, const float* gptr) {
    asm volatile("cp.async.cg.shared.global [%0], [%1], 16;"
                 :: "r"(saddr), "l"(gptr));
}
__device__ __forceinline__ void cp_commit() {
    asm volatile("cp.async.commit_group;");
}
template <int N> __device__ __forceinline__ void cp_wait() {
    asm volatile("cp.async.wait_group %0;" :: "n"(N));
}

__global__ __launch_bounds__(THREADS, 3)   // 56-reg cap, 3 CTAs/SM
void corr_win_kernel(const float* __restrict__ x, float* __restrict__ out)
{
    __shared__ float buf[NBUF][STRIDE][NF];   // raw -> normalized in place

    const int tid  = threadIdx.x;
    const int warp = tid >> 5;
    const int lane = tid & 31;
    const int w0   = blockIdx.x * WPC;

    const uint32_t sbase = (uint32_t)__cvta_generic_to_shared(buf);

    // ---- prologue: prefetch windows 0 and 1 into slabs 0, 1 --------------
    if (tid < SLAB / 4) {   // 320 threads x 16B = 5120B
        cp_async16(sbase + (0 * SLAB + tid * 4) * 4,
                   x + (size_t)(w0 + 0) * SLAB + tid * 4);
    }
    cp_commit();
    if (tid < SLAB / 4) {
        cp_async16(sbase + (1 * SLAB + tid * 4) * 4,
                   x + (size_t)(w0 + 1) * SLAB + tid * 4);
    }
    cp_commit();

    // warp task geometry (fixed across windows)
    const int i0 = (int)c_bi[warp] * 16;
    const int jb = (int)c_jc[warp] * 64;
    const int j0 = jb + lane;          // coalesced column 1
    const int j1 = jb + 32 + lane;     // coalesced column 2
    const bool full = (jb + 64 <= i0); // fully interior tile

    for (int w = 0; w < WPC; ++w) {
        // wait for window w's slab (keep 1 group in flight, 0 on last)
        if (w < WPC - 1) cp_wait<1>(); else cp_wait<0>();
        __syncthreads();   // slab (w%3) visible to all threads

        // prefetch window w+2 into slab (w+2)%3  (== slab (w-1)%3, whose
        // compute finished before this sync)
        if (w + 2 < WPC) {
            if (tid < SLAB / 4) {
                cp_async16(sbase + (((w + 2) % NBUF) * SLAB + tid * 4) * 4,
                           x + (size_t)(w0 + w + 2) * SLAB + tid * 4);
            }
            cp_commit();
        }

        float (*ms)[NF] = buf[w % NBUF];

        // ---- normalize in place: center + scale by 1/||.|| ---------------
        if (tid < NF) {
            float v[STRIDE];
            #pragma unroll
            for (int s = 0; s < STRIDE; ++s) v[s] = ms[s][tid];
            float sum = 0.f;
            #pragma unroll
            for (int s = 0; s < STRIDE; ++s) sum += v[s];
            const float mean = sum * (1.0f / STRIDE);
            float s2 = 0.f;
            #pragma unroll
            for (int s = 0; s < STRIDE; ++s) {
                v[s] -= mean;
                s2 = fmaf(v[s], v[s], s2);
            }
            const float invn = (s2 > 0.f) ? rsqrtf(s2) : 0.f;  // divide_no_nan
            #pragma unroll
            for (int s = 0; s < STRIDE; ++s) ms[s][tid] = v[s] * invn;
        }
        __syncthreads();

        // ---- 16x64 warp tile, packed f32x2 FMAs ---------------------------
        unsigned long long acc0[8], acc1[8];
        #pragma unroll
        for (int p = 0; p < 8; ++p) { acc0[p] = 0ULL; acc1[p] = 0ULL; }

        #pragma unroll
        for (int s = 0; s < STRIDE; ++s) {
            const float b0 = ms[s][j0];    // coalesced
            const float b1 = ms[s][j1];    // coalesced
            unsigned long long bb0, bb1;
            asm("mov.b64 %0, {%1, %1};" : "=l"(bb0) : "r"(__float_as_uint(b0)));
            asm("mov.b64 %0, {%1, %1};" : "=l"(bb1) : "r"(__float_as_uint(b1)));
            #pragma unroll
            for (int q = 0; q < 4; ++q) {
                const ulonglong2 A = *(const ulonglong2*)&ms[s][i0 + 4 * q];
                asm("fma.rn.f32x2 %0, %1, %2, %0;" : "+l"(acc0[2*q  ]) : "l"(A.x), "l"(bb0));
                asm("fma.rn.f32x2 %0, %1, %2, %0;" : "+l"(acc1[2*q  ]) : "l"(A.x), "l"(bb1));
                asm("fma.rn.f32x2 %0, %1, %2, %0;" : "+l"(acc0[2*q+1]) : "l"(A.y), "l"(bb0));
                asm("fma.rn.f32x2 %0, %1, %2, %0;" : "+l"(acc1[2*q+1]) : "l"(A.y), "l"(bb1));
            }
        }

        // ---- stores: incremental triangular base, full/partial ------------
        float* __restrict__ ow = out + (size_t)(w0 + w) * PAIRS;
        int i    = i0;
        int base = (i0 * (i0 - 1)) >> 1;
        if (full) {
            #pragma unroll
            for (int p = 0; p < 8; ++p) {
                unsigned int l0, h0, l1, h1;
                asm("mov.b64 {%0, %1}, %2;" : "=r"(l0), "=r"(h0) : "l"(acc0[p]));
                asm("mov.b64 {%0, %1}, %2;" : "=r"(l1), "=r"(h1) : "l"(acc1[p]));
                __stcs(&ow[base + j0], __uint_as_float(l0));
                __stcs(&ow[base + j1], __uint_as_float(l1));
                base += i; ++i;
                __stcs(&ow[base + j0], __uint_as_float(h0));
                __stcs(&ow[base + j1], __uint_as_float(h1));
                base += i; ++i;
            }
        } else {
            #pragma unroll
            for (int p = 0; p < 8; ++p) {
                unsigned int l0, h0, l1, h1;
                asm("mov.b64 {%0, %1}, %2;" : "=r"(l0), "=r"(h0) : "l"(acc0[p]));
                asm("mov.b64 {%0, %1}, %2;" : "=r"(l1), "=r"(h1) : "l"(acc1[p]));
                if (j0 < i) __stcs(&ow[base + j0], __uint_as_float(l0));
                if (j1 < i) __stcs(&ow[base + j1], __uint_as_float(l1));
                base += i; ++i;
                if (j0 < i) __stcs(&ow[base + j0], __uint_as_float(h0));
                if (j1 < i) __stcs(&ow[base + j1], __uint_as_float(h1));
                base += i; ++i;
            }
        }
    }
}

extern "C" void kernel_launch(void* const* d_in, const int* in_sizes, int n_in,
                              void* d_out, int out_size)
{
    const float* x = (const float*)d_in[0];
    float* out     = (float*)d_out;
    int n_windows  = in_sizes[0] / (STRIDE * NF);   // 6400
    corr_win_kernel<<<n_windows / WPC, THREADS>>>(x, out);
}

// round 10
// speedup vs baseline: 1.6280x; 1.6280x over previous
#include <cuda_runtime.h>
#include <cstdint>

#define STRIDE   10
#define NF       128
#define PAIRS    8128      // 128*127/2
#define NTASKS   12        // 16-row blocks x 64-col chunks covering lower triangle
#define THREADS  384       // 12 warps, exactly 1 task each
#define WPC      4         // windows per CTA
#define SLAB     (STRIDE * NF)   // 1280 floats = 5120 B

// task -> (16-row block index, 64-col chunk index)
__constant__ unsigned char c_bi[NTASKS] = {0,1,2,3,4,4,5,5,6,6,7,7};
__constant__ unsigned char c_jc[NTASKS] = {0,0,0,0,0,1,0,1,0,1,0,1};

__device__ __forceinline__ void cp_async16(uint32_t saddr, const float* gptr) {
    asm volatile("cp.async.cg.shared.global [%0], [%1], 16;"
                 :: "r"(saddr), "l"(gptr));
}

__global__ __launch_bounds__(THREADS, 3)   // 56-reg cap (R8-proven for this body)
void corr_win_kernel(const float* __restrict__ x, float* __restrict__ out)
{
    __shared__ __align__(16) float buf[WPC][STRIDE][NF];   // 20 KB

    const int tid  = threadIdx.x;
    const int warp = tid >> 5;
    const int lane = tid & 31;
    const int w0   = blockIdx.x * WPC;

    // ---- prefetch ALL 4 slabs in one group, pay LDG latency once ---------
    const uint32_t sbase = (uint32_t)__cvta_generic_to_shared(buf);
    if (tid < SLAB / 4) {   // 320 threads x 16B per slab
        const float* gp = x + (size_t)w0 * SLAB + tid * 4;
        #pragma unroll
        for (int w = 0; w < WPC; ++w)
            cp_async16(sbase + (w * SLAB + tid * 4) * 4, gp + w * SLAB);
    }
    asm volatile("cp.async.commit_group;");

    // warp task geometry (fixed across windows)
    const int i0 = (int)c_bi[warp] * 16;
    const int jb = (int)c_jc[warp] * 64;
    const int j0 = jb + lane;          // coalesced column 1
    const int j1 = jb + 32 + lane;     // coalesced column 2
    const bool full = (jb + 64 <= i0); // fully interior tile

    asm volatile("cp.async.wait_group 0;");
    __syncthreads();   // all 4 slabs visible to all threads

    #pragma unroll
    for (int w = 0; w < WPC; ++w) {
        float (*ms)[NF] = buf[w];      // static index (unrolled)

        // ---- normalize in place: center + scale by 1/||.|| ---------------
        // (writes buf[w] only; other warps may still read buf[w-1] — safe)
        if (tid < NF) {
            float v[STRIDE];
            #pragma unroll
            for (int s = 0; s < STRIDE; ++s) v[s] = ms[s][tid];
            float sum = 0.f;
            #pragma unroll
            for (int s = 0; s < STRIDE; ++s) sum += v[s];
            const float mean = sum * (1.0f / STRIDE);
            float s2 = 0.f;
            #pragma unroll
            for (int s = 0; s < STRIDE; ++s) {
                v[s] -= mean;
                s2 = fmaf(v[s], v[s], s2);
            }
            const float invn = (s2 > 0.f) ? rsqrtf(s2) : 0.f;  // divide_no_nan
            #pragma unroll
            for (int s = 0; s < STRIDE; ++s) ms[s][tid] = v[s] * invn;
        }
        __syncthreads();

        // ---- 16x64 warp tile, packed f32x2 FMAs ---------------------------
        unsigned long long acc0[8], acc1[8];
        #pragma unroll
        for (int p = 0; p < 8; ++p) { acc0[p] = 0ULL; acc1[p] = 0ULL; }

        #pragma unroll
        for (int s = 0; s < STRIDE; ++s) {
            const float b0 = ms[s][j0];    // coalesced
            const float b1 = ms[s][j1];    // coalesced
            unsigned long long bb0, bb1;
            asm("mov.b64 %0, {%1, %1};" : "=l"(bb0) : "r"(__float_as_uint(b0)));
            asm("mov.b64 %0, {%1, %1};" : "=l"(bb1) : "r"(__float_as_uint(b1)));
            #pragma unroll
            for (int q = 0; q < 4; ++q) {
                const ulonglong2 A = *(const ulonglong2*)&ms[s][i0 + 4 * q];
                asm("fma.rn.f32x2 %0, %1, %2, %0;" : "+l"(acc0[2*q  ]) : "l"(A.x), "l"(bb0));
                asm("fma.rn.f32x2 %0, %1, %2, %0;" : "+l"(acc1[2*q  ]) : "l"(A.x), "l"(bb1));
                asm("fma.rn.f32x2 %0, %1, %2, %0;" : "+l"(acc0[2*q+1]) : "l"(A.y), "l"(bb0));
                asm("fma.rn.f32x2 %0, %1, %2, %0;" : "+l"(acc1[2*q+1]) : "l"(A.y), "l"(bb1));
            }
        }

        // ---- stores: incremental triangular base, full/partial ------------
        float* __restrict__ ow = out + (size_t)(w0 + w) * PAIRS;
        int i    = i0;
        int base = (i0 * (i0 - 1)) >> 1;
        if (full) {
            #pragma unroll
            for (int p = 0; p < 8; ++p) {
                unsigned int l0, h0, l1, h1;
                asm("mov.b64 {%0, %1}, %2;" : "=r"(l0), "=r"(h0) : "l"(acc0[p]));
                asm("mov.b64 {%0, %1}, %2;" : "=r"(l1), "=r"(h1) : "l"(acc1[p]));
                __stcs(&ow[base + j0], __uint_as_float(l0));
                __stcs(&ow[base + j1], __uint_as_float(l1));
                base += i; ++i;
                __stcs(&ow[base + j0], __uint_as_float(h0));
                __stcs(&ow[base + j1], __uint_as_float(h1));
                base += i; ++i;
            }
        } else {
            #pragma unroll
            for (int p = 0; p < 8; ++p) {
                unsigned int l0, h0, l1, h1;
                asm("mov.b64 {%0, %1}, %2;" : "=r"(l0), "=r"(h0) : "l"(acc0[p]));
                asm("mov.b64 {%0, %1}, %2;" : "=r"(l1), "=r"(h1) : "l"(acc1[p]));
                if (j0 < i) __stcs(&ow[base + j0], __uint_as_float(l0));
                if (j1 < i) __stcs(&ow[base + j1], __uint_as_float(l1));
                base += i; ++i;
                if (j0 < i) __stcs(&ow[base + j0], __uint_as_float(h0));
                if (j1 < i) __stcs(&ow[base + j1], __uint_as_float(h1));
                base += i; ++i;
            }
        }
    }
}

extern "C" void kernel_launch(void* const* d_in, const int* in_sizes, int n_in,
                              void* d_out, int out_size)
{
    const float* x = (const float*)d_in[0];
    float* out     = (float*)d_out;
    int n_windows  = in_sizes[0] / (STRIDE * NF);   // 6400
    corr_win_kernel<<<n_windows / WPC, THREADS>>>(x, out);
}

// round 11
// speedup vs baseline: 1.6746x; 1.0286x over previous
#include <cuda_runtime.h>
#include <cstdint>

#define STRIDE   10
#define NF       128
#define PAIRS    8128      // 128*127/2
#define NTASKS   12        // 16-row blocks x 64-col chunks covering lower triangle
#define THREADS  384       // 12 warps, exactly 1 task each
#define WPC      4         // windows per CTA
#define SLAB     (STRIDE * NF)   // 1280 floats = 5120 B

// task -> (16-row block index, 64-col chunk index)
__constant__ unsigned char c_bi[NTASKS] = {0,1,2,3,4,4,5,5,6,6,7,7};
__constant__ unsigned char c_jc[NTASKS] = {0,0,0,0,0,1,0,1,0,1,0,1};

__device__ __forceinline__ void cp_async16(uint32_t saddr, const float* gptr) {
    asm volatile("cp.async.cg.shared.global [%0], [%1], 16;"
                 :: "r"(saddr), "l"(gptr));
}

__global__ __launch_bounds__(THREADS, 3)
void corr_win_kernel(const float* __restrict__ x, float* __restrict__ out)
{
    __shared__ __align__(16) float buf[WPC][STRIDE][NF];   // 20 KB

    const int tid  = threadIdx.x;
    const int warp = tid >> 5;
    const int lane = tid & 31;
    const int w0   = blockIdx.x * WPC;

    // ---- prefetch ALL 4 slabs in one group --------------------------------
    const uint32_t sbase = (uint32_t)__cvta_generic_to_shared(buf);
    if (tid < SLAB / 4) {   // 320 threads x 16B per slab
        const float* gp = x + (size_t)w0 * SLAB + tid * 4;
        #pragma unroll
        for (int w = 0; w < WPC; ++w)
            cp_async16(sbase + (w * SLAB + tid * 4) * 4, gp + w * SLAB);
    }
    asm volatile("cp.async.commit_group;");

    // warp task geometry (fixed across windows)
    const int i0 = (int)c_bi[warp] * 16;
    const int jb = (int)c_jc[warp] * 64;
    const int j0 = jb + lane;          // coalesced column 1
    const int j1 = jb + 32 + lane;     // coalesced column 2
    const bool full = (jb + 64 <= i0); // fully interior tile

    asm volatile("cp.async.wait_group 0;");
    __syncthreads();   // barrier #1: all 4 raw slabs visible

    // ---- normalize ALL 4x128 columns with ALL 384 threads -----------------
    // c = w*128 + f ; strided so every warp does useful work (no idle phase)
    #pragma unroll
    for (int c = tid; c < WPC * NF; c += THREADS) {
        const int wi = c >> 7;         // window index
        const int f  = c & 127;        // feature/column
        float v[STRIDE];
        #pragma unroll
        for (int s = 0; s < STRIDE; ++s) v[s] = buf[wi][s][f];
        float sum = 0.f;
        #pragma unroll
        for (int s = 0; s < STRIDE; ++s) sum += v[s];
        const float mean = sum * (1.0f / STRIDE);
        float s2 = 0.f;
        #pragma unroll
        for (int s = 0; s < STRIDE; ++s) {
            v[s] -= mean;
            s2 = fmaf(v[s], v[s], s2);
        }
        const float invn = (s2 > 0.f) ? rsqrtf(s2) : 0.f;  // divide_no_nan
        #pragma unroll
        for (int s = 0; s < STRIDE; ++s) buf[wi][s][f] = v[s] * invn;
    }
    __syncthreads();   // barrier #2 (LAST barrier): all columns normalized

    // ---- compute all 4 windows barrier-free -------------------------------
    #pragma unroll
    for (int w = 0; w < WPC; ++w) {
        float (*ms)[NF] = buf[w];

        unsigned long long acc0[8], acc1[8];
        #pragma unroll
        for (int p = 0; p < 8; ++p) { acc0[p] = 0ULL; acc1[p] = 0ULL; }

        #pragma unroll
        for (int s = 0; s < STRIDE; ++s) {
            const float b0 = ms[s][j0];    // coalesced
            const float b1 = ms[s][j1];    // coalesced
            unsigned long long bb0, bb1;
            asm("mov.b64 %0, {%1, %1};" : "=l"(bb0) : "r"(__float_as_uint(b0)));
            asm("mov.b64 %0, {%1, %1};" : "=l"(bb1) : "r"(__float_as_uint(b1)));
            #pragma unroll
            for (int q = 0; q < 4; ++q) {
                const ulonglong2 A = *(const ulonglong2*)&ms[s][i0 + 4 * q];
                asm("fma.rn.f32x2 %0, %1, %2, %0;" : "+l"(acc0[2*q  ]) : "l"(A.x), "l"(bb0));
                asm("fma.rn.f32x2 %0, %1, %2, %0;" : "+l"(acc1[2*q  ]) : "l"(A.x), "l"(bb1));
                asm("fma.rn.f32x2 %0, %1, %2, %0;" : "+l"(acc0[2*q+1]) : "l"(A.y), "l"(bb0));
                asm("fma.rn.f32x2 %0, %1, %2, %0;" : "+l"(acc1[2*q+1]) : "l"(A.y), "l"(bb1));
            }
        }

        // ---- stores: incremental triangular base, full/partial ------------
        float* __restrict__ ow = out + (size_t)(w0 + w) * PAIRS;
        int i    = i0;
        int base = (i0 * (i0 - 1)) >> 1;
        if (full) {
            #pragma unroll
            for (int p = 0; p < 8; ++p) {
                unsigned int l0, h0, l1, h1;
                asm("mov.b64 {%0, %1}, %2;" : "=r"(l0), "=r"(h0) : "l"(acc0[p]));
                asm("mov.b64 {%0, %1}, %2;" : "=r"(l1), "=r"(h1) : "l"(acc1[p]));
                __stcs(&ow[base + j0], __uint_as_float(l0));
                __stcs(&ow[base + j1], __uint_as_float(l1));
                base += i; ++i;
                __stcs(&ow[base + j0], __uint_as_float(h0));
                __stcs(&ow[base + j1], __uint_as_float(h1));
                base += i; ++i;
            }
        } else {
            #pragma unroll
            for (int p = 0; p < 8; ++p) {
                unsigned int l0, h0, l1, h1;
                asm("mov.b64 {%0, %1}, %2;" : "=r"(l0), "=r"(h0) : "l"(acc0[p]));
                asm("mov.b64 {%0, %1}, %2;" : "=r"(l1), "=r"(h1) : "l"(acc1[p]));
                if (j0 < i) __stcs(&ow[base + j0], __uint_as_float(l0));
                if (j1 < i) __stcs(&ow[base + j1], __uint_as_float(l1));
                base += i; ++i;
                if (j0 < i) __stcs(&ow[base + j0], __uint_as_float(h0));
                if (j1 < i) __stcs(&ow[base + j1], __uint_as_float(h1));
                base += i; ++i;
            }
        }
    }
}

extern "C" void kernel_launch(void* const* d_in, const int* in_sizes, int n_in,
                              void* d_out, int out_size)
{
    const float* x = (const float*)d_in[0];
    float* out     = (float*)d_out;
    int n_windows  = in_sizes[0] / (STRIDE * NF);   // 6400
    corr_win_kernel<<<n_windows / WPC, THREADS>>>(x, out);
}

// round 12
// speedup vs baseline: 1.7194x; 1.0267x over previous
#include <cuda_runtime.h>
#include <cstdint>

#define STRIDE   10
#define NF       128
#define PAIRS    8128      // 128*127/2
#define NTASKS   24        // 8-row blocks x 64-col chunks covering lower triangle
#define THREADS  384       // 12 warps x 2 tasks each
#define WPC      4         // windows per CTA
#define SLAB     (STRIDE * NF)   // 1280 floats = 5120 B

// task -> (8-row block index, 64-col chunk index)
__constant__ unsigned char c_b8[NTASKS] =
    {0,1,2,3,4,5,6,7, 8,8, 9,9, 10,10, 11,11, 12,12, 13,13, 14,14, 15,15};
__constant__ unsigned char c_jc[NTASKS] =
    {0,0,0,0,0,0,0,0, 0,1, 0,1, 0,1,   0,1,   0,1,   0,1,   0,1,   0,1};

__device__ __forceinline__ void cp_async16(uint32_t saddr, const float* gptr) {
    asm volatile("cp.async.cg.shared.global [%0], [%1], 16;"
                 :: "r"(saddr), "l"(gptr));
}

__global__ __launch_bounds__(THREADS, 4)   // 40-reg cap -> 4 CTAs/SM (48 warps)
void corr_win_kernel(const float* __restrict__ x, float* __restrict__ out)
{
    __shared__ __align__(16) float buf[WPC][STRIDE][NF];   // 20 KB

    const int tid  = threadIdx.x;
    const int warp = tid >> 5;
    const int lane = tid & 31;
    const int w0   = blockIdx.x * WPC;

    // ---- prefetch ALL 4 slabs in one group --------------------------------
    const uint32_t sbase = (uint32_t)__cvta_generic_to_shared(buf);
    if (tid < SLAB / 4) {   // 320 threads x 16B per slab
        const float* gp = x + (size_t)w0 * SLAB + tid * 4;
        #pragma unroll
        for (int w = 0; w < WPC; ++w)
            cp_async16(sbase + (w * SLAB + tid * 4) * 4, gp + w * SLAB);
    }
    asm volatile("cp.async.commit_group;");
    asm volatile("cp.async.wait_group 0;");
    __syncthreads();   // barrier #1: all 4 raw slabs visible

    // ---- normalize ALL 4x128 columns with ALL 384 threads -----------------
    #pragma unroll
    for (int c = tid; c < WPC * NF; c += THREADS) {
        const int wi = c >> 7;
        const int f  = c & 127;
        float v[STRIDE];
        #pragma unroll
        for (int s = 0; s < STRIDE; ++s) v[s] = buf[wi][s][f];
        float sum = 0.f;
        #pragma unroll
        for (int s = 0; s < STRIDE; ++s) sum += v[s];
        const float mean = sum * (1.0f / STRIDE);
        float s2 = 0.f;
        #pragma unroll
        for (int s = 0; s < STRIDE; ++s) {
            v[s] -= mean;
            s2 = fmaf(v[s], v[s], s2);
        }
        const float invn = (s2 > 0.f) ? rsqrtf(s2) : 0.f;  // divide_no_nan
        #pragma unroll
        for (int s = 0; s < STRIDE; ++s) buf[wi][s][f] = v[s] * invn;
    }
    __syncthreads();   // barrier #2 (last): all columns normalized

    // ---- compute: 4 windows x 2 tasks of 8x64, barrier-free ---------------
    #pragma unroll
    for (int w = 0; w < WPC; ++w) {
        float (*ms)[NF] = buf[w];
        float* __restrict__ ow = out + (size_t)(w0 + w) * PAIRS;

        #pragma unroll
        for (int k = 0; k < 2; ++k) {
            const int t  = warp * 2 + k;
            const int i0 = (int)c_b8[t] * 8;
            const int jb = (int)c_jc[t] * 64;
            const int j0 = jb + lane;
            const int j1 = jb + 32 + lane;
            const bool full = (jb + 64 <= i0);

            // 4 packed acc pairs per column set = 8 rows paired (i, i+1)
            unsigned long long acc0[4], acc1[4];
            #pragma unroll
            for (int p = 0; p < 4; ++p) { acc0[p] = 0ULL; acc1[p] = 0ULL; }

            #pragma unroll
            for (int s = 0; s < STRIDE; ++s) {
                const float b0 = ms[s][j0];
                const float b1 = ms[s][j1];
                unsigned long long bb0, bb1;
                asm("mov.b64 %0, {%1, %1};" : "=l"(bb0) : "r"(__float_as_uint(b0)));
                asm("mov.b64 %0, {%1, %1};" : "=l"(bb1) : "r"(__float_as_uint(b1)));
                #pragma unroll
                for (int q = 0; q < 2; ++q) {
                    const ulonglong2 A = *(const ulonglong2*)&ms[s][i0 + 4 * q];
                    asm("fma.rn.f32x2 %0, %1, %2, %0;" : "+l"(acc0[2*q  ]) : "l"(A.x), "l"(bb0));
                    asm("fma.rn.f32x2 %0, %1, %2, %0;" : "+l"(acc1[2*q  ]) : "l"(A.x), "l"(bb1));
                    asm("fma.rn.f32x2 %0, %1, %2, %0;" : "+l"(acc0[2*q+1]) : "l"(A.y), "l"(bb0));
                    asm("fma.rn.f32x2 %0, %1, %2, %0;" : "+l"(acc1[2*q+1]) : "l"(A.y), "l"(bb1));
                }
            }

            // ---- stores: incremental triangular base, full/partial --------
            int i    = i0;
            int base = (i0 * (i0 - 1)) >> 1;
            if (full) {
                #pragma unroll
                for (int p = 0; p < 4; ++p) {
                    unsigned int l0, h0, l1, h1;
                    asm("mov.b64 {%0, %1}, %2;" : "=r"(l0), "=r"(h0) : "l"(acc0[p]));
                    asm("mov.b64 {%0, %1}, %2;" : "=r"(l1), "=r"(h1) : "l"(acc1[p]));
                    __stcs(&ow[base + j0], __uint_as_float(l0));
                    __stcs(&ow[base + j1], __uint_as_float(l1));
                    base += i; ++i;
                    __stcs(&ow[base + j0], __uint_as_float(h0));
                    __stcs(&ow[base + j1], __uint_as_float(h1));
                    base += i; ++i;
                }
            } else {
                #pragma unroll
                for (int p = 0; p < 4; ++p) {
                    unsigned int l0, h0, l1, h1;
                    asm("mov.b64 {%0, %1}, %2;" : "=r"(l0), "=r"(h0) : "l"(acc0[p]));
                    asm("mov.b64 {%0, %1}, %2;" : "=r"(l1), "=r"(h1) : "l"(acc1[p]));
                    if (j0 < i) __stcs(&ow[base + j0], __uint_as_float(l0));
                    if (j1 < i) __stcs(&ow[base + j1], __uint_as_float(l1));
                    base += i; ++i;
                    if (j0 < i) __stcs(&ow[base + j0], __uint_as_float(h0));
                    if (j1 < i) __stcs(&ow[base + j1], __uint_as_float(h1));
                    base += i; ++i;
                }
            }
        }
    }
}

extern "C" void kernel_launch(void* const* d_in, const int* in_sizes, int n_in,
                              void* d_out, int out_size)
{
    const float* x = (const float*)d_in[0];
    float* out     = (float*)d_out;
    int n_windows  = in_sizes[0] / (STRIDE * NF);   // 6400
    corr_win_kernel<<<n_windows / WPC, THREADS>>>(x, out);
}